// round 1
// baseline (speedup 1.0000x reference)
#include <cuda_runtime.h>
#include <cstdint>

#define N_ATOMS 4096
#define NG      12
#define N_GRID  1728
#define N_TOT   5824
#define HID     256
#define KNBR    32
#define NRBF    64
#define TAB     4096
#define CAP     1024
#define TKTILE  512
#define BM      64
#define CUTOFF  12.0f
#define BIGV    1e9f

// ---------------- scratch (static __device__, no allocs) ----------------
__device__ float g_px[N_TOT], g_py[N_TOT], g_pz[N_TOT], g_ps[N_TOT];
__device__ int   g_zz[N_TOT];
__device__ unsigned char g_valid[N_TOT];
__device__ int   g_nbr[N_TOT * KNBR];
__device__ float g_dq[N_TOT * KNBR];
__device__ float g_E1[125 * HID];        // embed @ W1
__device__ float g_Wr1[NRBF * HID];      // Wrbf @ W1
__device__ float2 g_T2[TAB * HID];       // table of g(d)=rbf(d)@Wr1, (T[i],T[i+1]) pairs
__device__ float g_s[N_TOT * HID];       // sum of silu over edges
__device__ int   g_cnt[N_TOT];

// ---------------- fast silu: no MUFU (exp2 poly + Newton rcp) -----------
__device__ __forceinline__ float fast_silu(float x) {
    // sigmoid(x) = 1/(1 + 2^(-x*log2 e))
    float t = -1.4426950408889634f * x;
    t = fminf(fmaxf(t, -126.0f), 126.0f);
    float fi = floorf(t);
    float f  = t - fi;
    float p = 1.5403530393e-4f;
    p = fmaf(p, f, 1.3333558146e-3f);
    p = fmaf(p, f, 9.6181291076e-3f);
    p = fmaf(p, f, 5.5504108665e-2f);
    p = fmaf(p, f, 2.4022650696e-1f);
    p = fmaf(p, f, 6.9314718056e-1f);
    p = fmaf(p, f, 1.0f);
    float e = __uint_as_float((unsigned)(((int)fi + 127) << 23)) * p; // 2^t
    float u = 1.0f + e;
    float r = __uint_as_float(0x7EF311C3u - __float_as_uint(u));      // ~1/u
    r = r * (2.0f - u * r);
    r = r * (2.0f - u * r);
    r = r * (2.0f - u * r);
    return x * r;
}

// ---------------- K1: positions / z / squared norms ---------------------
__global__ void k_setup(const float* __restrict__ pos,
                        const int* __restrict__ anum,
                        const float* __restrict__ cell) {
    int i = blockIdx.x * blockDim.x + threadIdx.x;
    if (i >= N_TOT) return;
    float x, y, z; int zz; unsigned char v;
    if (i < N_ATOMS) {
        x = pos[i * 3 + 0]; y = pos[i * 3 + 1]; z = pos[i * 3 + 2];
        zz = anum[i]; v = 1;
    } else {
        int g = i - N_ATOMS;
        int ia = g / (NG * NG), ib = (g / NG) % NG, ic = g % NG;
        float fa = (float)ia / NG, fb = (float)ib / NG, fc = (float)ic / NG;
        x = fa * cell[0] + fb * cell[3] + fc * cell[6];
        y = fa * cell[1] + fb * cell[4] + fc * cell[7];
        z = fa * cell[2] + fb * cell[5] + fc * cell[8];
        zz = 120; v = 0;   // validity filled by k_vmask
    }
    g_px[i] = x; g_py[i] = y; g_pz[i] = z;
    g_ps[i] = (x * x + y * y) + z * z;
    g_zz[i] = zz; g_valid[i] = v;
}

// ---------------- K2: repulsion mask for grid nodes ---------------------
__global__ void k_vmask() {
    __shared__ float4 tile[256];
    int g = blockIdx.x * blockDim.x + threadIdx.x;
    bool act = g < N_GRID;
    float x = 0, y = 0, z = 0, s = 0, mind2 = BIGV;
    if (act) {
        int i = N_ATOMS + g;
        x = g_px[i]; y = g_py[i]; z = g_pz[i]; s = g_ps[i];
    }
    for (int base = 0; base < N_ATOMS; base += 256) {
        int a = base + threadIdx.x;
        tile[threadIdx.x] = make_float4(g_px[a], g_py[a], g_pz[a], g_ps[a]);
        __syncthreads();
        if (act) {
            #pragma unroll 4
            for (int e = 0; e < 256; e++) {
                float4 q = tile[e];
                float d2 = s + q.w - 2.0f * ((x * q.x + y * q.y) + z * q.z);
                mind2 = fminf(mind2, d2);
            }
        }
        __syncthreads();
    }
    if (act) g_valid[N_ATOMS + g] = (mind2 >= 4.0f) ? 1 : 0; // d>=2 <=> d2>=4
}

// ---------------- K3: E1 = embed@W1 (125 rows), Wr1 = Wrbf@W1 (64 rows) -
__global__ void k_premm(const float* __restrict__ embed,
                        const float* __restrict__ Wrbf,
                        const float* __restrict__ W1) {
    __shared__ float row[HID];
    int r = blockIdx.x;
    const float* src = (r < 125) ? (embed + r * HID) : (Wrbf + (r - 125) * HID);
    row[threadIdx.x] = src[threadIdx.x];
    __syncthreads();
    int t = threadIdx.x;
    float acc = 0.0f;
    for (int k2 = 0; k2 < HID; k2++)
        acc = fmaf(row[k2], W1[k2 * HID + t], acc);
    if (r < 125) g_E1[r * HID + t] = acc;
    else         g_Wr1[(r - 125) * HID + t] = acc;
}

// ---------------- K4: tabulate g(d) = rbf(d)@Wr1 on [0,12] --------------
__global__ void k_table() {
    extern __shared__ float sm[];
    float* wr = sm;              // NRBF*HID
    float* rb = sm + NRBF * HID; // NRBF
    for (int idx = threadIdx.x; idx < NRBF * HID; idx += blockDim.x)
        wr[idx] = g_Wr1[idx];
    __syncthreads();
    int t = threadIdx.x;
    const float inv_w = (float)NRBF / CUTOFF;  // 1/width, width = 12/64
    for (int rr = 0; rr < TAB / 128; rr++) {
        int r = blockIdx.x * (TAB / 128) + rr;
        float d = (float)r * (CUTOFF / (TAB - 1));
        if (t < NRBF) {
            float c = (float)t * (CUTOFF / (NRBF - 1)); // linspace(0,12,64)
            float u = (d - c) * inv_w;
            rb[t] = __expf(-0.5f * u * u);
        }
        __syncthreads();
        float acc = 0.0f;
        #pragma unroll
        for (int j = 0; j < NRBF; j++)
            acc = fmaf(rb[j], wr[j * HID + t], acc);
        g_T2[r * HID + t].x = acc;
        if (r > 0) g_T2[(r - 1) * HID + t].y = acc;  // interleaved lerp pair
        __syncthreads();
    }
}

// ---------------- K5: top-K neighbors (compaction + warp argmin) --------
__global__ void k_topk() {
    extern __shared__ unsigned long long smem_ll[];
    unsigned long long* lists = smem_ll;                          // 8*CAP u64
    float4* tile = (float4*)(lists + 8 * CAP);                    // TKTILE
    unsigned char* tval = (unsigned char*)(tile + TKTILE);        // TKTILE
    int* scnt = (int*)(tval + TKTILE);                            // 8
    int warp = threadIdx.x >> 5, lane = threadIdx.x & 31;
    int row = blockIdx.x * 8 + warp;
    if (lane == 0) scnt[warp] = 0;
    __syncthreads();
    bool rv = g_valid[row] != 0;
    float xi = g_px[row], yi = g_py[row], zi = g_pz[row], si = g_ps[row];
    unsigned long long* list = lists + warp * CAP;

    for (int base = 0; base < N_TOT; base += TKTILE) {
        for (int idx = threadIdx.x; idx < TKTILE; idx += 256) {
            int j = base + idx;
            if (j < N_TOT) {
                tile[idx] = make_float4(g_px[j], g_py[j], g_pz[j], g_ps[j]);
                tval[idx] = g_valid[j];
            } else tval[idx] = 0;
        }
        __syncthreads();
        int n = min(TKTILE, N_TOT - base);
        if (rv) {
            for (int e0 = 0; e0 < n; e0 += 32) {
                int e = e0 + lane;
                bool ok = false; unsigned long long key = 0;
                if (e < n && tval[e]) {
                    float4 q = tile[e];
                    float d2 = si + q.w - 2.0f * ((xi * q.x + yi * q.y) + zi * q.z);
                    int j = base + e;
                    if (j != row && d2 <= 145.0f) {
                        ok = true;
                        key = ((unsigned long long)__float_as_uint(fmaxf(d2, 0.0f)) << 32)
                              | (unsigned)j;
                    }
                }
                unsigned m = __ballot_sync(0xffffffffu, ok);
                if (m) {
                    int leader = __ffs(m) - 1;
                    int basei = 0;
                    if (lane == leader) basei = atomicAdd(&scnt[warp], __popc(m));
                    basei = __shfl_sync(0xffffffffu, basei, leader);
                    if (ok) {
                        int p = basei + __popc(m & ((1u << lane) - 1));
                        if (p < CAP) list[p] = key;
                    }
                }
            }
        }
        __syncthreads();
    }

    int L = rv ? min(scnt[warp], CAP) : 0;
    for (int e = 0; e < KNBR; e++) {
        unsigned long long best = ~0ull;
        for (int idx = lane; idx < L; idx += 32) {
            unsigned long long v = list[idx];
            best = (v < best) ? v : best;
        }
        for (int o = 16; o; o >>= 1) {
            unsigned long long ov = __shfl_down_sync(0xffffffffu, best, o);
            best = (ov < best) ? ov : best;
        }
        best = __shfl_sync(0xffffffffu, best, 0);
        if (lane == 0) {
            if (best == ~0ull) {
                g_nbr[row * KNBR + e] = 0;
                g_dq[row * KNBR + e] = BIGV;
            } else {
                float d2v = __uint_as_float((unsigned)(best >> 32));
                g_nbr[row * KNBR + e] = (int)(unsigned)(best & 0xffffffffu);
                g_dq[row * KNBR + e] = sqrtf(fmaxf(d2v, 1e-12f));
            }
        }
        if (best != ~0ull) {
            for (int idx = lane; idx < L; idx += 32)
                if (list[idx] == best) list[idx] = ~0ull;
        }
    }
}

// ---------------- K6: per-edge z1 + silu, accumulate per node -----------
__global__ void __launch_bounds__(256) k_edges(const float* __restrict__ b1) {
    __shared__ float sd[KNBR];
    __shared__ int   szj[KNBR];
    int i = blockIdx.x, t = threadIdx.x;
    if (t < KNBR) {
        sd[t] = g_dq[i * KNBR + t];
        szj[t] = g_zz[g_nbr[i * KNBR + t]];
    }
    __syncthreads();
    float base = g_E1[g_zz[i] * HID + t] + b1[t];
    float acc = 0.0f; int cnt = 0;
    const float sc = (float)(TAB - 1) / CUTOFF;
    for (int e = 0; e < KNBR; e++) {
        float d = sd[e];
        if (d <= CUTOFF) {
            cnt++;
            float u = d * sc;
            int i0 = (int)u; i0 = min(i0, TAB - 2);
            float f = u - (float)i0;
            float2 g2 = g_T2[i0 * HID + t];
            float pn = g_E1[szj[e] * HID + t];
            float z1 = base + pn + fmaf(f, g2.y - g2.x, g2.x);
            acc += fast_silu(z1);
        }
    }
    g_s[i * HID + t] = acc;
    if (t == 0) g_cnt[i] = cnt;
}

// ---------------- K7: feat = h + s@W2 + cnt*b2 --------------------------
__global__ void __launch_bounds__(256) k_final(const float* __restrict__ embed,
                                               const float* __restrict__ W2,
                                               const float* __restrict__ b2,
                                               float* __restrict__ out) {
    extern __shared__ float ss[];  // BM*HID
    int m0 = blockIdx.x * BM, t = threadIdx.x;
    for (int idx = t; idx < BM * HID; idx += blockDim.x)
        ss[idx] = g_s[m0 * HID + idx];
    __syncthreads();
    float acc[BM];
    #pragma unroll
    for (int m = 0; m < BM; m++) acc[m] = 0.0f;
    for (int k2 = 0; k2 < HID; k2++) {
        float w = W2[k2 * HID + t];
        #pragma unroll
        for (int m = 0; m < BM; m++)
            acc[m] = fmaf(ss[m * HID + k2], w, acc[m]);
    }
    float b2t = b2[t];
    for (int m = 0; m < BM; m++) {
        int nd = m0 + m;
        float v = 0.0f;
        if (g_valid[nd])
            v = embed[g_zz[nd] * HID + t] + acc[m] + (float)g_cnt[nd] * b2t;
        out[nd * HID + t] = v;
    }
}

// ---------------- K8: masks ---------------------------------------------
__global__ void k_masks(float* __restrict__ out) {
    int i = blockIdx.x * blockDim.x + threadIdx.x;
    if (i >= N_TOT) return;
    float vn = (i >= N_ATOMS && g_valid[i]) ? 1.0f : 0.0f;
    float pn = (i < N_ATOMS) ? 1.0f : 0.0f;  // atoms always valid, z != 120
    out[N_TOT * HID + i] = vn;
    out[N_TOT * HID + N_TOT + i] = pn;
}

// ---------------- launch -------------------------------------------------
extern "C" void kernel_launch(void* const* d_in, const int* in_sizes, int n_in,
                              void* d_out, int out_size) {
    const float* pos   = (const float*)d_in[0];
    const int*   anum  = (const int*)d_in[1];
    const float* cell  = (const float*)d_in[2];
    const float* embed = (const float*)d_in[3];
    const float* Wrbf  = (const float*)d_in[4];
    const float* W1    = (const float*)d_in[5];
    const float* b1    = (const float*)d_in[6];
    const float* W2    = (const float*)d_in[7];
    const float* b2    = (const float*)d_in[8];
    float* out = (float*)d_out;

    const int smem_table = (NRBF * HID + NRBF) * 4;                        // ~65.8 KB
    const int smem_topk  = 8 * CAP * 8 + TKTILE * 16 + TKTILE + 8 * 4;     // ~74.3 KB
    const int smem_final = BM * HID * 4;                                   // 64 KB
    cudaFuncSetAttribute(k_table, cudaFuncAttributeMaxDynamicSharedMemorySize, smem_table);
    cudaFuncSetAttribute(k_topk,  cudaFuncAttributeMaxDynamicSharedMemorySize, smem_topk);
    cudaFuncSetAttribute(k_final, cudaFuncAttributeMaxDynamicSharedMemorySize, smem_final);

    k_setup<<<(N_TOT + 255) / 256, 256>>>(pos, anum, cell);
    k_vmask<<<(N_GRID + 255) / 256, 256>>>();
    k_premm<<<125 + NRBF, 256>>>(embed, Wrbf, W1);
    k_table<<<128, 256, smem_table>>>();
    k_topk<<<N_TOT / 8, 256, smem_topk>>>();
    k_edges<<<N_TOT, 256>>>(b1);
    k_final<<<N_TOT / BM, 256, smem_final>>>(embed, W2, b2, out);
    if (out_size >= N_TOT * HID + 2 * N_TOT)
        k_masks<<<(N_TOT + 255) / 256, 256>>>(out);
}

// round 2
// speedup vs baseline: 1.6079x; 1.6079x over previous
#include <cuda_runtime.h>
#include <cstdint>

#define N_ATOMS 4096
#define NG      12
#define N_GRID  1728
#define N_TOT   5824
#define HID     256
#define KNBR    32
#define NRBF    64
#define TAB     4096
#define CAP     1024
#define TKTILE  512
#define CUTOFF  12.0f
#define BIGV    1e9f

// ---------------- scratch (static __device__, no allocs) ----------------
__device__ float g_px[N_TOT], g_py[N_TOT], g_pz[N_TOT], g_ps[N_TOT];
__device__ int   g_zz[N_TOT];
__device__ unsigned char g_valid[N_TOT];
__device__ unsigned g_mind2u[N_GRID];
__device__ int   g_nbr[N_TOT * KNBR];
__device__ float g_dq[N_TOT * KNBR];
__device__ float g_E1[125 * HID];        // embed @ W1
__device__ float g_Wr1[NRBF * HID];      // Wrbf @ W1
__device__ float2 g_T2[TAB * HID];       // table of g(d)=rbf(d)@Wr1, lerp pairs
__device__ float g_s[N_TOT * HID];       // sum of silu over edges
__device__ int   g_cnt[N_TOT];

// ---------------- packed f32x2 helpers ----------------------------------
__device__ __forceinline__ unsigned long long pk2(float lo, float hi) {
    unsigned long long r;
    asm("mov.b64 %0,{%1,%2};" : "=l"(r) : "f"(lo), "f"(hi));
    return r;
}
__device__ __forceinline__ void fma2(unsigned long long& d,
                                     unsigned long long a, unsigned long long b) {
    asm("fma.rn.f32x2 %0,%1,%2,%0;" : "+l"(d) : "l"(a), "l"(b));
}
__device__ __forceinline__ float2 up2(unsigned long long v) {
    float2 f;
    asm("mov.b64 {%0,%1},%2;" : "=f"(f.x), "=f"(f.y) : "l"(v));
    return f;
}

// ---------------- fast silu: no MUFU (exp2 poly + Newton rcp) -----------
__device__ __forceinline__ float fast_silu(float x) {
    float t = -1.4426950408889634f * x;
    t = fminf(fmaxf(t, -126.0f), 126.0f);
    float fi = floorf(t);
    float f  = t - fi;
    float p = 1.5403530393e-4f;
    p = fmaf(p, f, 1.3333558146e-3f);
    p = fmaf(p, f, 9.6181291076e-3f);
    p = fmaf(p, f, 5.5504108665e-2f);
    p = fmaf(p, f, 2.4022650696e-1f);
    p = fmaf(p, f, 6.9314718056e-1f);
    p = fmaf(p, f, 1.0f);
    float e = __uint_as_float((unsigned)(((int)fi + 127) << 23)) * p;
    float u = 1.0f + e;
    float r = __uint_as_float(0x7EF311C3u - __float_as_uint(u));
    r = r * (2.0f - u * r);
    r = r * (2.0f - u * r);
    r = r * (2.0f - u * r);
    return x * r;
}

// ---------------- K1: positions / z / squared norms ---------------------
__global__ void k_setup(const float* __restrict__ pos,
                        const int* __restrict__ anum,
                        const float* __restrict__ cell) {
    int i = blockIdx.x * blockDim.x + threadIdx.x;
    if (i >= N_TOT) return;
    if (i < N_GRID) g_mind2u[i] = 0x7F7FFFFFu;  // +FLT_MAX
    float x, y, z; int zz; unsigned char v;
    if (i < N_ATOMS) {
        x = pos[i * 3 + 0]; y = pos[i * 3 + 1]; z = pos[i * 3 + 2];
        zz = anum[i]; v = 1;
    } else {
        int g = i - N_ATOMS;
        int ia = g / (NG * NG), ib = (g / NG) % NG, ic = g % NG;
        float fa = (float)ia / NG, fb = (float)ib / NG, fc = (float)ic / NG;
        x = fa * cell[0] + fb * cell[3] + fc * cell[6];
        y = fa * cell[1] + fb * cell[4] + fc * cell[7];
        z = fa * cell[2] + fb * cell[5] + fc * cell[8];
        zz = 120; v = 0;
    }
    g_px[i] = x; g_py[i] = y; g_pz[i] = z;
    g_ps[i] = (x * x + y * y) + z * z;
    g_zz[i] = zz; g_valid[i] = v;
}

// ---------------- K2: repulsion mask (atom-split, atomicMin) ------------
#define VSPLIT 8
#define VCHUNK (N_ATOMS / VSPLIT)   // 512
__global__ void k_vmask() {
    __shared__ float4 tile[VCHUNK];
    int node = blockIdx.x * blockDim.x + threadIdx.x;
    int a0 = blockIdx.y * VCHUNK;
    for (int idx = threadIdx.x; idx < VCHUNK; idx += blockDim.x) {
        int a = a0 + idx;
        tile[idx] = make_float4(g_px[a], g_py[a], g_pz[a], g_ps[a]);
    }
    __syncthreads();
    if (node >= N_GRID) return;
    int i = N_ATOMS + node;
    float x = g_px[i], y = g_py[i], z = g_pz[i], s = g_ps[i];
    float mind2 = BIGV;
    #pragma unroll 8
    for (int e = 0; e < VCHUNK; e++) {
        float4 q = tile[e];
        float d2 = s + q.w - 2.0f * ((x * q.x + y * q.y) + z * q.z);
        mind2 = fminf(mind2, d2);
    }
    atomicMin(&g_mind2u[node], __float_as_uint(fmaxf(mind2, 0.0f)));
}

// ---------------- K3: E1 = embed@W1, Wr1 = Wrbf@W1; finalize validity ---
__global__ void __launch_bounds__(256) k_premm(const float* __restrict__ embed,
                                               const float* __restrict__ Wrbf,
                                               const float* __restrict__ W1) {
    // fused validity finalize (grid nodes) — stream order guarantees vmask done
    int gid = blockIdx.x * blockDim.x + threadIdx.x;
    if (gid < N_GRID) {
        bool ok = __uint_as_float(g_mind2u[gid]) >= 4.0f;  // d>=2 <=> d2>=4
        g_valid[N_ATOMS + gid] = ok ? 1 : 0;
        if (!ok) g_ps[N_ATOMS + gid] += 3.0e9f;  // auto-fail distance cutoff
    }

    __shared__ float srows[8 * HID];
    int r0 = blockIdx.x * 8;
    for (int idx = threadIdx.x; idx < 8 * HID; idx += 256) {
        int rr = idx >> 8, k = idx & 255;
        int row = r0 + rr;
        float v = 0.0f;
        if (row < 125) v = embed[row * HID + k];
        else if (row < 189) v = Wrbf[(row - 125) * HID + k];
        srows[idx] = v;
    }
    __syncthreads();
    int t = threadIdx.x;
    float acc[8];
    #pragma unroll
    for (int r = 0; r < 8; r++) acc[r] = 0.0f;
    for (int k = 0; k < HID; k++) {
        float w = W1[k * HID + t];
        #pragma unroll
        for (int r = 0; r < 8; r++)
            acc[r] = fmaf(srows[r * HID + k], w, acc[r]);
    }
    #pragma unroll
    for (int r = 0; r < 8; r++) {
        int row = r0 + r;
        if (row < 125) g_E1[row * HID + t] = acc[r];
        else if (row < 189) g_Wr1[(row - 125) * HID + t] = acc[r];
    }
}

// ---------------- K4: tabulate g(d)=rbf(d)@Wr1, reg-resident Wr1 --------
#define TROWS 16
__global__ void __launch_bounds__(256) k_table() {
    __shared__ float rb[NRBF * TROWS];   // [j][r] layout, 4KB
    int t = threadIdx.x;
    int row0 = blockIdx.x * TROWS;
    float wr[NRBF];
    #pragma unroll
    for (int j = 0; j < NRBF; j++) wr[j] = g_Wr1[j * HID + t];

    const float step = CUTOFF / (TAB - 1);
    const float inv_w = (float)NRBF / CUTOFF;
    #pragma unroll
    for (int p = 0; p < (NRBF * TROWS) / 256; p++) {
        int idx = t + 256 * p;
        int j = idx >> 4, r = idx & 15;
        float d = (float)(row0 + r) * step;
        float c = (float)j * (CUTOFF / (NRBF - 1));
        float u = (d - c) * inv_w;
        rb[idx] = __expf(-0.5f * u * u);
    }
    __syncthreads();

    float acc[TROWS];
    #pragma unroll
    for (int r = 0; r < TROWS; r++) acc[r] = 0.0f;
    #pragma unroll
    for (int j = 0; j < NRBF; j++) {
        float w = wr[j];
        const float4* rp = (const float4*)&rb[j * TROWS];
        #pragma unroll
        for (int g4 = 0; g4 < TROWS / 4; g4++) {
            float4 v = rp[g4];
            acc[g4 * 4 + 0] = fmaf(v.x, w, acc[g4 * 4 + 0]);
            acc[g4 * 4 + 1] = fmaf(v.y, w, acc[g4 * 4 + 1]);
            acc[g4 * 4 + 2] = fmaf(v.z, w, acc[g4 * 4 + 2]);
            acc[g4 * 4 + 3] = fmaf(v.w, w, acc[g4 * 4 + 3]);
        }
    }
    #pragma unroll
    for (int r = 0; r < TROWS; r++) {
        int row = row0 + r;
        g_T2[row * HID + t].x = acc[r];
        if (row > 0) g_T2[(row - 1) * HID + t].y = acc[r];
    }
}

// ---------------- K5: top-K (compaction, no atomics, + warp argmin) -----
__global__ void k_topk() {
    extern __shared__ unsigned long long smem_ll[];
    unsigned long long* lists = smem_ll;                 // 8*CAP u64
    float4* tile = (float4*)(lists + 8 * CAP);           // TKTILE
    int warp = threadIdx.x >> 5, lane = threadIdx.x & 31;
    int row = blockIdx.x * 8 + warp;
    bool rv = g_valid[row] != 0;
    float xi = g_px[row], yi = g_py[row], zi = g_pz[row], si = g_ps[row];
    unsigned long long* list = lists + warp * CAP;
    unsigned lanemask_lt = (1u << lane) - 1u;
    int cnt = 0;

    for (int base = 0; base < N_TOT; base += TKTILE) {
        for (int idx = threadIdx.x; idx < TKTILE; idx += 256) {
            int j = base + idx;
            tile[idx] = (j < N_TOT)
                ? make_float4(g_px[j], g_py[j], g_pz[j], g_ps[j])
                : make_float4(0.f, 0.f, 0.f, 3.0e9f);
        }
        __syncthreads();
        if (rv) {
            int n = min(TKTILE, N_TOT - base);
            for (int e0 = 0; e0 < n; e0 += 32) {
                int e = e0 + lane;
                bool ok = false; unsigned long long key = 0;
                float4 q = tile[e];
                float d2 = si + q.w - 2.0f * ((xi * q.x + yi * q.y) + zi * q.z);
                int j = base + e;
                if (e < n && j != row && d2 <= 145.0f) {
                    ok = true;
                    key = ((unsigned long long)__float_as_uint(fmaxf(d2, 0.0f)) << 32)
                          | (unsigned)j;
                }
                unsigned m = __ballot_sync(0xffffffffu, ok);
                if (m) {
                    if (ok) {
                        int p = cnt + __popc(m & lanemask_lt);
                        if (p < CAP) list[p] = key;
                    }
                    cnt += __popc(m);
                }
            }
        }
        __syncthreads();
    }

    int L = rv ? min(cnt, CAP) : 0;
    for (int e = 0; e < KNBR; e++) {
        unsigned long long best = ~0ull;
        for (int idx = lane; idx < L; idx += 32) {
            unsigned long long v = list[idx];
            best = (v < best) ? v : best;
        }
        for (int o = 16; o; o >>= 1) {
            unsigned long long ov = __shfl_down_sync(0xffffffffu, best, o);
            best = (ov < best) ? ov : best;
        }
        best = __shfl_sync(0xffffffffu, best, 0);
        if (lane == 0) {
            if (best == ~0ull) {
                g_nbr[row * KNBR + e] = 0;
                g_dq[row * KNBR + e] = BIGV;
            } else {
                float d2v = __uint_as_float((unsigned)(best >> 32));
                g_nbr[row * KNBR + e] = (int)(unsigned)(best & 0xffffffffu);
                g_dq[row * KNBR + e] = sqrtf(fmaxf(d2v, 1e-12f));
            }
        }
        if (best != ~0ull) {
            for (int idx = lane; idx < L; idx += 32)
                if (list[idx] == best) list[idx] = ~0ull;
        }
    }
}

// ---------------- K6: per-edge z1 + silu, accumulate per node -----------
__global__ void __launch_bounds__(256) k_edges(const float* __restrict__ b1) {
    __shared__ float sd[KNBR];
    __shared__ int   szj[KNBR];
    int i = blockIdx.x, t = threadIdx.x;
    if (t < KNBR) {
        sd[t] = g_dq[i * KNBR + t];
        szj[t] = g_zz[g_nbr[i * KNBR + t]];
    }
    __syncthreads();
    float base = g_E1[g_zz[i] * HID + t] + b1[t];
    float acc = 0.0f; int cnt = 0;
    const float sc = (float)(TAB - 1) / CUTOFF;
    for (int e = 0; e < KNBR; e++) {
        float d = sd[e];
        if (d <= CUTOFF) {
            cnt++;
            float u = d * sc;
            int i0 = (int)u; i0 = min(i0, TAB - 2);
            float f = u - (float)i0;
            float2 g2 = g_T2[i0 * HID + t];
            float pn = g_E1[szj[e] * HID + t];
            float z1 = base + pn + fmaf(f, g2.y - g2.x, g2.x);
            acc += fast_silu(z1);
        }
    }
    g_s[i * HID + t] = acc;
    if (t == 0) g_cnt[i] = cnt;
}

// ---------------- K7: feat = h + s@W2 + cnt*b2 (reg-tiled f32x2 GEMM) ---
#define FBM 64
#define FBN 128
#define FBK 32
__global__ void __launch_bounds__(256) k_final(const float* __restrict__ embed,
                                               const float* __restrict__ W2,
                                               const float* __restrict__ b2,
                                               float* __restrict__ out) {
    __shared__ float As[FBM * FBK];      // [m][k], 8KB
    __shared__ float Bs[FBK * FBN];      // [k][n], 16KB
    int tid = threadIdx.x;
    int tx = tid & 31;       // 32 col-groups of 4
    int ty = tid >> 5;       // 8 row-groups of 8
    int m0 = blockIdx.x * FBM;
    int n0 = blockIdx.y * FBN;

    unsigned long long acc[16];  // 8 rows x 2 col-pairs
    #pragma unroll
    for (int q = 0; q < 16; q++) acc[q] = 0ull;

    for (int k0 = 0; k0 < HID; k0 += FBK) {
        #pragma unroll
        for (int p = 0; p < (FBM * FBK) / 256; p++) {
            int idx = tid + 256 * p;
            int m = idx >> 5, k = idx & 31;
            As[idx] = g_s[(m0 + m) * HID + k0 + k];
        }
        #pragma unroll
        for (int p = 0; p < (FBK * FBN) / 256; p++) {
            int idx = tid + 256 * p;
            int kk = idx >> 7, n = idx & 127;
            Bs[idx] = W2[(k0 + kk) * HID + n0 + n];
        }
        __syncthreads();
        #pragma unroll
        for (int kk = 0; kk < FBK; kk++) {
            float4 bv = *(const float4*)&Bs[kk * FBN + tx * 4];
            unsigned long long b01 = pk2(bv.x, bv.y);
            unsigned long long b23 = pk2(bv.z, bv.w);
            #pragma unroll
            for (int r = 0; r < 8; r++) {
                float a = As[(ty * 8 + r) * FBK + kk];
                unsigned long long aa = pk2(a, a);
                fma2(acc[r * 2 + 0], aa, b01);
                fma2(acc[r * 2 + 1], aa, b23);
            }
        }
        __syncthreads();
    }

    int cbase = n0 + tx * 4;
    float4 b2v = *(const float4*)&b2[cbase];
    #pragma unroll
    for (int r = 0; r < 8; r++) {
        int node = m0 + ty * 8 + r;
        float2 p0 = up2(acc[r * 2 + 0]);
        float2 p1 = up2(acc[r * 2 + 1]);
        float4 res = make_float4(0.f, 0.f, 0.f, 0.f);
        if (g_valid[node]) {
            const float* em = embed + g_zz[node] * HID + cbase;
            float cf = (float)g_cnt[node];
            res.x = em[0] + p0.x + cf * b2v.x;
            res.y = em[1] + p0.y + cf * b2v.y;
            res.z = em[2] + p1.x + cf * b2v.z;
            res.w = em[3] + p1.y + cf * b2v.w;
        }
        *(float4*)&out[node * HID + cbase] = res;
    }

    // fused masks (one block column only)
    if (blockIdx.y == 0 && tid < FBM) {
        int node = m0 + tid;
        float vn = (node >= N_ATOMS && g_valid[node]) ? 1.0f : 0.0f;
        float pn = (node < N_ATOMS) ? 1.0f : 0.0f;
        out[N_TOT * HID + node] = vn;
        out[N_TOT * HID + N_TOT + node] = pn;
    }
}

// ---------------- launch -------------------------------------------------
extern "C" void kernel_launch(void* const* d_in, const int* in_sizes, int n_in,
                              void* d_out, int out_size) {
    const float* pos   = (const float*)d_in[0];
    const int*   anum  = (const int*)d_in[1];
    const float* cell  = (const float*)d_in[2];
    const float* embed = (const float*)d_in[3];
    const float* Wrbf  = (const float*)d_in[4];
    const float* W1    = (const float*)d_in[5];
    const float* b1    = (const float*)d_in[6];
    const float* W2    = (const float*)d_in[7];
    const float* b2    = (const float*)d_in[8];
    float* out = (float*)d_out;

    const int smem_topk = 8 * CAP * 8 + TKTILE * 16;   // 73728
    static int init_done = 0;
    cudaFuncSetAttribute(k_topk, cudaFuncAttributeMaxDynamicSharedMemorySize, smem_topk);
    (void)init_done;

    k_setup<<<(N_TOT + 255) / 256, 256>>>(pos, anum, cell);
    k_vmask<<<dim3((N_GRID + 255) / 256, VSPLIT), 256>>>();
    k_premm<<<(189 + 7) / 8, 256>>>(embed, Wrbf, W1);
    k_table<<<TAB / TROWS, 256>>>();
    k_topk<<<N_TOT / 8, 256, smem_topk>>>();
    k_edges<<<N_TOT, 256>>>(b1);
    k_final<<<dim3(N_TOT / FBM, HID / FBN), 256>>>(embed, W2, b2, out);
}

// round 3
// speedup vs baseline: 1.8594x; 1.1564x over previous
#include <cuda_runtime.h>
#include <cuda_fp16.h>
#include <cstdint>

#define N_ATOMS 4096
#define NG      12
#define N_GRID  1728
#define N_TOT   5824
#define HID     256
#define KNBR    32
#define NRBF    64
#define TAB     4096
#define NCAP    256
#define FCAP    768
#define CAP     1024
#define TKTILE  512
#define CUTOFF  12.0f
#define BIGV    1e9f
#define NEAR2   36.0f

// ---------------- scratch (static __device__, no allocs) ----------------
__device__ float g_px[N_TOT], g_py[N_TOT], g_pz[N_TOT], g_ps[N_TOT];
__device__ int   g_zz[N_TOT];
__device__ unsigned char g_valid[N_TOT];
__device__ unsigned g_mind2u[N_GRID];
__device__ int   g_nbr[N_TOT * KNBR];
__device__ float g_dq[N_TOT * KNBR];
__device__ float g_E1[125 * HID];        // embed @ W1
__device__ float g_Wr1[NRBF * HID];      // Wrbf @ W1
__device__ __half2 g_Th[TAB * HID];      // half2 lerp pairs (T[r], T[r+1])
__device__ float g_s[N_TOT * HID];       // sum of silu over edges
__device__ int   g_cnt[N_TOT];

// ---------------- packed f32x2 helpers ----------------------------------
__device__ __forceinline__ unsigned long long pk2(float lo, float hi) {
    unsigned long long r;
    asm("mov.b64 %0,{%1,%2};" : "=l"(r) : "f"(lo), "f"(hi));
    return r;
}
__device__ __forceinline__ void fma2(unsigned long long& d,
                                     unsigned long long a, unsigned long long b) {
    asm("fma.rn.f32x2 %0,%1,%2,%0;" : "+l"(d) : "l"(a), "l"(b));
}
__device__ __forceinline__ float2 up2(unsigned long long v) {
    float2 f;
    asm("mov.b64 {%0,%1},%2;" : "=f"(f.x), "=f"(f.y) : "l"(v));
    return f;
}

// ---------------- fast silu: no MUFU (exp2 poly + Newton rcp) -----------
__device__ __forceinline__ float fast_silu(float x) {
    float t = -1.4426950408889634f * x;
    t = fminf(fmaxf(t, -126.0f), 126.0f);
    float fi = floorf(t);
    float f  = t - fi;
    float p = 1.5403530393e-4f;
    p = fmaf(p, f, 1.3333558146e-3f);
    p = fmaf(p, f, 9.6181291076e-3f);
    p = fmaf(p, f, 5.5504108665e-2f);
    p = fmaf(p, f, 2.4022650696e-1f);
    p = fmaf(p, f, 6.9314718056e-1f);
    p = fmaf(p, f, 1.0f);
    float e = __uint_as_float((unsigned)(((int)fi + 127) << 23)) * p;
    float u = 1.0f + e;
    float r = __uint_as_float(0x7EF311C3u - __float_as_uint(u));
    r = r * (2.0f - u * r);
    r = r * (2.0f - u * r);
    r = r * (2.0f - u * r);
    return x * r;
}

// ---------------- K1: positions / z / squared norms ---------------------
__global__ void k_setup(const float* __restrict__ pos,
                        const int* __restrict__ anum,
                        const float* __restrict__ cell) {
    int i = blockIdx.x * blockDim.x + threadIdx.x;
    if (i >= N_TOT) return;
    if (i < N_GRID) g_mind2u[i] = 0x7F7FFFFFu;
    float x, y, z; int zz; unsigned char v;
    if (i < N_ATOMS) {
        x = pos[i * 3 + 0]; y = pos[i * 3 + 1]; z = pos[i * 3 + 2];
        zz = anum[i]; v = 1;
    } else {
        int g = i - N_ATOMS;
        int ia = g / (NG * NG), ib = (g / NG) % NG, ic = g % NG;
        float fa = (float)ia / NG, fb = (float)ib / NG, fc = (float)ic / NG;
        x = fa * cell[0] + fb * cell[3] + fc * cell[6];
        y = fa * cell[1] + fb * cell[4] + fc * cell[7];
        z = fa * cell[2] + fb * cell[5] + fc * cell[8];
        zz = 120; v = 0;
    }
    g_px[i] = x; g_py[i] = y; g_pz[i] = z;
    g_ps[i] = (x * x + y * y) + z * z;
    g_zz[i] = zz; g_valid[i] = v;
}

// ---------------- K2: repulsion mask (atom-split, atomicMin) ------------
#define VSPLIT 16
#define VCHUNK (N_ATOMS / VSPLIT)   // 256
__global__ void k_vmask() {
    __shared__ float4 tile[VCHUNK];
    int node = blockIdx.x * blockDim.x + threadIdx.x;
    int a0 = blockIdx.y * VCHUNK;
    {
        int a = a0 + threadIdx.x;
        tile[threadIdx.x] = make_float4(g_px[a], g_py[a], g_pz[a], g_ps[a]);
    }
    __syncthreads();
    if (node >= N_GRID) return;
    int i = N_ATOMS + node;
    float x = g_px[i], y = g_py[i], z = g_pz[i], s = g_ps[i];
    float mind2 = BIGV;
    #pragma unroll 8
    for (int e = 0; e < VCHUNK; e++) {
        float4 q = tile[e];
        float d2 = s + q.w - 2.0f * ((x * q.x + y * q.y) + z * q.z);
        mind2 = fminf(mind2, d2);
    }
    atomicMin(&g_mind2u[node], __float_as_uint(fmaxf(mind2, 0.0f)));
}

// ---------------- K3: E1 = embed@W1, Wr1 = Wrbf@W1; finalize validity ---
__global__ void __launch_bounds__(256) k_premm(const float* __restrict__ embed,
                                               const float* __restrict__ Wrbf,
                                               const float* __restrict__ W1) {
    int gid = blockIdx.x * blockDim.x + threadIdx.x;
    if (gid < N_GRID) {
        bool ok = __uint_as_float(g_mind2u[gid]) >= 4.0f;
        g_valid[N_ATOMS + gid] = ok ? 1 : 0;
        if (!ok) g_ps[N_ATOMS + gid] += 3.0e9f;  // auto-fail distance cutoff
    }

    __shared__ float srows[8 * HID];
    int r0 = blockIdx.x * 8;
    for (int idx = threadIdx.x; idx < 8 * HID; idx += 256) {
        int rr = idx >> 8, k = idx & 255;
        int row = r0 + rr;
        float v = 0.0f;
        if (row < 125) v = embed[row * HID + k];
        else if (row < 189) v = Wrbf[(row - 125) * HID + k];
        srows[idx] = v;
    }
    __syncthreads();
    int t = threadIdx.x;
    float acc[8];
    #pragma unroll
    for (int r = 0; r < 8; r++) acc[r] = 0.0f;
    for (int k = 0; k < HID; k++) {
        float w = W1[k * HID + t];
        #pragma unroll
        for (int r = 0; r < 8; r++)
            acc[r] = fmaf(srows[r * HID + k], w, acc[r]);
    }
    #pragma unroll
    for (int r = 0; r < 8; r++) {
        int row = r0 + r;
        if (row < 125) g_E1[row * HID + t] = acc[r];
        else if (row < 189) g_Wr1[(row - 125) * HID + t] = acc[r];
    }
}

// ---------------- K4: tabulate g(d)=rbf(d)@Wr1 -> half2 pairs -----------
#define TROWS 16
__global__ void __launch_bounds__(256) k_table() {
    __shared__ float rb[NRBF * TROWS];   // [j][r], float4-friendly over r
    __shared__ float rbx[NRBF];          // extra column: row row0+TROWS
    int t = threadIdx.x;
    int row0 = blockIdx.x * TROWS;
    float wr[NRBF];
    #pragma unroll
    for (int j = 0; j < NRBF; j++) wr[j] = g_Wr1[j * HID + t];

    const float step = CUTOFF / (TAB - 1);
    const float inv_w = (float)NRBF / CUTOFF;
    #pragma unroll
    for (int p = 0; p < (NRBF * TROWS) / 256; p++) {
        int idx = t + 256 * p;
        int j = idx >> 4, r = idx & 15;
        float d = (float)(row0 + r) * step;
        float c = (float)j * (CUTOFF / (NRBF - 1));
        float u = (d - c) * inv_w;
        rb[idx] = __expf(-0.5f * u * u);
    }
    if (t < NRBF) {
        float d = (float)(row0 + TROWS) * step;
        float c = (float)t * (CUTOFF / (NRBF - 1));
        float u = (d - c) * inv_w;
        rbx[t] = __expf(-0.5f * u * u);
    }
    __syncthreads();

    float acc[TROWS + 1];
    #pragma unroll
    for (int r = 0; r <= TROWS; r++) acc[r] = 0.0f;
    #pragma unroll
    for (int j = 0; j < NRBF; j++) {
        float w = wr[j];
        const float4* rp = (const float4*)&rb[j * TROWS];
        #pragma unroll
        for (int g4 = 0; g4 < TROWS / 4; g4++) {
            float4 v = rp[g4];
            acc[g4 * 4 + 0] = fmaf(v.x, w, acc[g4 * 4 + 0]);
            acc[g4 * 4 + 1] = fmaf(v.y, w, acc[g4 * 4 + 1]);
            acc[g4 * 4 + 2] = fmaf(v.z, w, acc[g4 * 4 + 2]);
            acc[g4 * 4 + 3] = fmaf(v.w, w, acc[g4 * 4 + 3]);
        }
        acc[TROWS] = fmaf(rbx[j], w, acc[TROWS]);
    }
    #pragma unroll
    for (int r = 0; r < TROWS; r++)
        g_Th[(row0 + r) * HID + t] = __floats2half2_rn(acc[r], acc[r + 1]);
}

// ---------------- K5: top-K (two-region compaction + successive-min) ----
__global__ void k_topk() {
    extern __shared__ unsigned long long smem_ll[];
    unsigned long long* lists = smem_ll;                 // 8*CAP u64
    float4* tile = (float4*)(lists + 8 * CAP);           // TKTILE
    int warp = threadIdx.x >> 5, lane = threadIdx.x & 31;
    int row = blockIdx.x * 8 + warp;
    bool rv = g_valid[row] != 0;
    float xi = g_px[row], yi = g_py[row], zi = g_pz[row], si = g_ps[row];
    unsigned long long* list = lists + warp * CAP;
    unsigned lanemask_lt = (1u << lane) - 1u;
    int nc = 0, fc = 0;

    for (int base = 0; base < N_TOT; base += TKTILE) {
        for (int idx = threadIdx.x; idx < TKTILE; idx += 256) {
            int j = base + idx;
            tile[idx] = (j < N_TOT)
                ? make_float4(g_px[j], g_py[j], g_pz[j], g_ps[j])
                : make_float4(0.f, 0.f, 0.f, 3.0e9f);
        }
        __syncthreads();
        if (rv) {
            int n = min(TKTILE, N_TOT - base);
            for (int e0 = 0; e0 < n; e0 += 32) {
                int e = e0 + lane;
                float4 q = tile[e];
                float d2 = si + q.w - 2.0f * ((xi * q.x + yi * q.y) + zi * q.z);
                int j = base + e;
                bool ok = (e < n) && (j != row) && (d2 <= 145.0f);
                bool nr = ok && (d2 <= NEAR2);
                bool fr = ok && !nr;
                unsigned long long key =
                    ((unsigned long long)__float_as_uint(fmaxf(d2, 0.0f)) << 32)
                    | (unsigned)j;
                unsigned mn = __ballot_sync(0xffffffffu, nr);
                unsigned mf = __ballot_sync(0xffffffffu, fr);
                if (nr) {
                    int p = nc + __popc(mn & lanemask_lt);
                    if (p < NCAP) list[p] = key;
                }
                if (fr) {
                    int p = fc + __popc(mf & lanemask_lt);
                    if (p < FCAP) list[NCAP + p] = key;
                }
                nc += __popc(mn);
                fc += __popc(mf);
            }
        }
        __syncthreads();
    }

    int len1 = 0, len2 = 0;
    if (rv) {
        len1 = min(nc, NCAP);
        len2 = (nc >= KNBR) ? 0 : min(fc, FCAP);
    }
    unsigned long long prev = 0;
    for (int e = 0; e < KNBR; e++) {
        unsigned long long best = ~0ull;
        for (int idx = lane; idx < len1; idx += 32) {
            unsigned long long v = list[idx];
            if (v > prev && v < best) best = v;
        }
        for (int idx = lane; idx < len2; idx += 32) {
            unsigned long long v = list[NCAP + idx];
            if (v > prev && v < best) best = v;
        }
        #pragma unroll
        for (int o = 16; o; o >>= 1) {
            unsigned long long ov = __shfl_down_sync(0xffffffffu, best, o);
            best = (ov < best) ? ov : best;
        }
        best = __shfl_sync(0xffffffffu, best, 0);
        if (lane == 0) {
            if (best == ~0ull) {
                g_nbr[row * KNBR + e] = 0;
                g_dq[row * KNBR + e] = BIGV;
            } else {
                float d2v = __uint_as_float((unsigned)(best >> 32));
                g_nbr[row * KNBR + e] = (int)(unsigned)(best & 0xffffffffu);
                g_dq[row * KNBR + e] = sqrtf(fmaxf(d2v, 1e-12f));
            }
        }
        prev = best;
    }
}

// ---------------- K6: per-edge z1 + silu, accumulate per node -----------
__global__ void __launch_bounds__(256) k_edges(const float* __restrict__ b1) {
    __shared__ float sd[KNBR];
    __shared__ int   szj[KNBR];
    int i = blockIdx.x, t = threadIdx.x;
    if (t < KNBR) {
        sd[t] = g_dq[i * KNBR + t];
        szj[t] = g_zz[g_nbr[i * KNBR + t]];
    }
    __syncthreads();
    float base = g_E1[g_zz[i] * HID + t] + b1[t];
    float acc = 0.0f; int cnt = 0;
    const float sc = (float)(TAB - 1) / CUTOFF;
    for (int e = 0; e < KNBR; e++) {
        float d = sd[e];
        if (d <= CUTOFF) {
            cnt++;
            float u = d * sc;
            int i0 = (int)u; i0 = min(i0, TAB - 2);
            float f = u - (float)i0;
            float2 g2 = __half22float2(g_Th[i0 * HID + t]);
            float pn = g_E1[szj[e] * HID + t];
            float z1 = base + pn + fmaf(f, g2.y - g2.x, g2.x);
            acc += fast_silu(z1);
        }
    }
    g_s[i * HID + t] = acc;
    if (t == 0) g_cnt[i] = cnt;
}

// ---------------- K7: feat = h + s@W2 + cnt*b2 (reg-tiled f32x2 GEMM) ---
#define FBM 64
#define FBN 128
#define FBK 32
__global__ void __launch_bounds__(256) k_final(const float* __restrict__ embed,
                                               const float* __restrict__ W2,
                                               const float* __restrict__ b2,
                                               float* __restrict__ out) {
    __shared__ float As[FBM * FBK];      // [m][k], 8KB
    __shared__ float Bs[FBK * FBN];      // [k][n], 16KB
    int tid = threadIdx.x;
    int tx = tid & 31;
    int ty = tid >> 5;
    int m0 = blockIdx.x * FBM;
    int n0 = blockIdx.y * FBN;

    unsigned long long acc[16];
    #pragma unroll
    for (int q = 0; q < 16; q++) acc[q] = 0ull;

    for (int k0 = 0; k0 < HID; k0 += FBK) {
        #pragma unroll
        for (int p = 0; p < (FBM * FBK) / 256; p++) {
            int idx = tid + 256 * p;
            int m = idx >> 5, k = idx & 31;
            As[idx] = g_s[(m0 + m) * HID + k0 + k];
        }
        #pragma unroll
        for (int p = 0; p < (FBK * FBN) / 256; p++) {
            int idx = tid + 256 * p;
            int kk = idx >> 7, n = idx & 127;
            Bs[idx] = W2[(k0 + kk) * HID + n0 + n];
        }
        __syncthreads();
        #pragma unroll
        for (int kk = 0; kk < FBK; kk++) {
            float4 bv = *(const float4*)&Bs[kk * FBN + tx * 4];
            unsigned long long b01 = pk2(bv.x, bv.y);
            unsigned long long b23 = pk2(bv.z, bv.w);
            #pragma unroll
            for (int r = 0; r < 8; r++) {
                float a = As[(ty * 8 + r) * FBK + kk];
                unsigned long long aa = pk2(a, a);
                fma2(acc[r * 2 + 0], aa, b01);
                fma2(acc[r * 2 + 1], aa, b23);
            }
        }
        __syncthreads();
    }

    int cbase = n0 + tx * 4;
    float4 b2v = *(const float4*)&b2[cbase];
    #pragma unroll
    for (int r = 0; r < 8; r++) {
        int node = m0 + ty * 8 + r;
        float2 p0 = up2(acc[r * 2 + 0]);
        float2 p1 = up2(acc[r * 2 + 1]);
        float4 res = make_float4(0.f, 0.f, 0.f, 0.f);
        if (g_valid[node]) {
            const float* em = embed + g_zz[node] * HID + cbase;
            float cf = (float)g_cnt[node];
            res.x = em[0] + p0.x + cf * b2v.x;
            res.y = em[1] + p0.y + cf * b2v.y;
            res.z = em[2] + p1.x + cf * b2v.z;
            res.w = em[3] + p1.y + cf * b2v.w;
        }
        *(float4*)&out[node * HID + cbase] = res;
    }

    if (blockIdx.y == 0 && tid < FBM) {
        int node = m0 + tid;
        float vn = (node >= N_ATOMS && g_valid[node]) ? 1.0f : 0.0f;
        float pn = (node < N_ATOMS) ? 1.0f : 0.0f;
        out[N_TOT * HID + node] = vn;
        out[N_TOT * HID + N_TOT + node] = pn;
    }
}

// ---------------- launch -------------------------------------------------
extern "C" void kernel_launch(void* const* d_in, const int* in_sizes, int n_in,
                              void* d_out, int out_size) {
    const float* pos   = (const float*)d_in[0];
    const int*   anum  = (const int*)d_in[1];
    const float* cell  = (const float*)d_in[2];
    const float* embed = (const float*)d_in[3];
    const float* Wrbf  = (const float*)d_in[4];
    const float* W1    = (const float*)d_in[5];
    const float* b1    = (const float*)d_in[6];
    const float* W2    = (const float*)d_in[7];
    const float* b2    = (const float*)d_in[8];
    float* out = (float*)d_out;

    const int smem_topk = 8 * CAP * 8 + TKTILE * 16;   // 73728
    cudaFuncSetAttribute(k_topk, cudaFuncAttributeMaxDynamicSharedMemorySize, smem_topk);

    k_setup<<<(N_TOT + 255) / 256, 256>>>(pos, anum, cell);
    k_vmask<<<dim3((N_GRID + 255) / 256, VSPLIT), 256>>>();
    k_premm<<<(189 + 7) / 8, 256>>>(embed, Wrbf, W1);
    k_table<<<TAB / TROWS, 256>>>();
    k_topk<<<N_TOT / 8, 256, smem_topk>>>();
    k_edges<<<N_TOT, 256>>>(b1);
    k_final<<<dim3(N_TOT / FBM, HID / FBN), 256>>>(embed, W2, b2, out);
}

// round 5
// speedup vs baseline: 2.1062x; 1.1327x over previous
#include <cuda_runtime.h>
#include <cuda_fp16.h>
#include <cstdint>

#define N_ATOMS 4096
#define NG      12
#define N_GRID  1728
#define N_TOT   5824
#define HID     256
#define KNBR    32
#define NRBF    64
#define TAB     4096
#define NCAP    256
#define FCAP    768
#define CAP     1024
#define TKTILE  512
#define CUTOFF  12.0f
#define BIGV    1e9f
#define NEAR2   36.0f

// ---------------- scratch (static __device__, no allocs) ----------------
__device__ float g_px[N_TOT], g_py[N_TOT], g_pz[N_TOT], g_ps[N_TOT];
__device__ int   g_zz[N_TOT];
__device__ unsigned char g_valid[N_TOT];
__device__ unsigned g_mind2u[N_GRID];
__device__ int   g_nbr[N_TOT * KNBR];
__device__ float g_dq[N_TOT * KNBR];
__device__ float g_E1[125 * HID];          // embed @ W1 (fp32, for own-row base)
__device__ __half2 g_E1h[125 * (HID / 2)]; // embed @ W1 (half2, for gathers)
__device__ float g_Wr1[NRBF * HID];        // Wrbf @ W1
__device__ __half2 g_Th[TAB * HID];        // half2 lerp pairs (T[r], T[r+1]) per channel
__device__ float g_s[N_TOT * HID];         // sum of silu over edges
__device__ int   g_cnt[N_TOT];

// ---------------- packed f32x2 helpers ----------------------------------
__device__ __forceinline__ unsigned long long pk2(float lo, float hi) {
    unsigned long long r;
    asm("mov.b64 %0,{%1,%2};" : "=l"(r) : "f"(lo), "f"(hi));
    return r;
}
__device__ __forceinline__ void fma2(unsigned long long& d,
                                     unsigned long long a, unsigned long long b) {
    asm("fma.rn.f32x2 %0,%1,%2,%0;" : "+l"(d) : "l"(a), "l"(b));
}
__device__ __forceinline__ float2 up2(unsigned long long v) {
    float2 f;
    asm("mov.b64 {%0,%1},%2;" : "=f"(f.x), "=f"(f.y) : "l"(v));
    return f;
}

// ---------------- fast silu (trimmed: no clamp, 2 Newton) ---------------
__device__ __forceinline__ float fast_silu(float x) {
    float t = -1.4426950408889634f * x;
    float fi = floorf(t);
    float f  = t - fi;
    float p = 1.5403530393e-4f;
    p = fmaf(p, f, 1.3333558146e-3f);
    p = fmaf(p, f, 9.6181291076e-3f);
    p = fmaf(p, f, 5.5504108665e-2f);
    p = fmaf(p, f, 2.4022650696e-1f);
    p = fmaf(p, f, 6.9314718056e-1f);
    p = fmaf(p, f, 1.0f);
    float e = __uint_as_float((unsigned)(((int)fi + 127) << 23)) * p;
    float u = 1.0f + e;
    float r = __uint_as_float(0x7EF311C3u - __float_as_uint(u));
    r = r * (2.0f - u * r);
    r = r * (2.0f - u * r);
    return x * r;
}

// ---------------- K1: positions / z / squared norms ---------------------
__global__ void k_setup(const float* __restrict__ pos,
                        const int* __restrict__ anum,
                        const float* __restrict__ cell) {
    int i = blockIdx.x * blockDim.x + threadIdx.x;
    if (i >= N_TOT) return;
    if (i < N_GRID) g_mind2u[i] = 0x7F7FFFFFu;
    float x, y, z; int zz; unsigned char v;
    if (i < N_ATOMS) {
        x = pos[i * 3 + 0]; y = pos[i * 3 + 1]; z = pos[i * 3 + 2];
        zz = anum[i]; v = 1;
    } else {
        int g = i - N_ATOMS;
        int ia = g / (NG * NG), ib = (g / NG) % NG, ic = g % NG;
        float fa = (float)ia / NG, fb = (float)ib / NG, fc = (float)ic / NG;
        x = fa * cell[0] + fb * cell[3] + fc * cell[6];
        y = fa * cell[1] + fb * cell[4] + fc * cell[7];
        z = fa * cell[2] + fb * cell[5] + fc * cell[8];
        zz = 120; v = 0;
    }
    g_px[i] = x; g_py[i] = y; g_pz[i] = z;
    g_ps[i] = (x * x + y * y) + z * z;
    g_zz[i] = zz; g_valid[i] = v;
}

// ---------------- K2: repulsion mask (atom-split, atomicMin) ------------
#define VSPLIT 16
#define VCHUNK (N_ATOMS / VSPLIT)   // 256
__global__ void k_vmask() {
    __shared__ float4 tile[VCHUNK];
    int node = blockIdx.x * blockDim.x + threadIdx.x;
    int a0 = blockIdx.y * VCHUNK;
    {
        int a = a0 + threadIdx.x;
        tile[threadIdx.x] = make_float4(g_px[a], g_py[a], g_pz[a], g_ps[a]);
    }
    __syncthreads();
    if (node >= N_GRID) return;
    int i = N_ATOMS + node;
    float x = g_px[i], y = g_py[i], z = g_pz[i], s = g_ps[i];
    float mind2 = BIGV;
    #pragma unroll 8
    for (int e = 0; e < VCHUNK; e++) {
        float4 q = tile[e];
        float d2 = s + q.w - 2.0f * ((x * q.x + y * q.y) + z * q.z);
        mind2 = fminf(mind2, d2);
    }
    atomicMin(&g_mind2u[node], __float_as_uint(fmaxf(mind2, 0.0f)));
}

// ---------------- K3: E1 = embed@W1 (+half2 copy), Wr1 = Wrbf@W1 --------
__global__ void __launch_bounds__(256) k_premm(const float* __restrict__ embed,
                                               const float* __restrict__ Wrbf,
                                               const float* __restrict__ W1) {
    int gid = blockIdx.x * blockDim.x + threadIdx.x;
    if (gid < N_GRID) {
        bool ok = __uint_as_float(g_mind2u[gid]) >= 4.0f;
        g_valid[N_ATOMS + gid] = ok ? 1 : 0;
        if (!ok) g_ps[N_ATOMS + gid] += 3.0e9f;  // auto-fail distance cutoff
    }

    __shared__ float srows[8 * HID];
    int r0 = blockIdx.x * 8;
    for (int idx = threadIdx.x; idx < 8 * HID; idx += 256) {
        int rr = idx >> 8, k = idx & 255;
        int row = r0 + rr;
        float v = 0.0f;
        if (row < 125) v = embed[row * HID + k];
        else if (row < 189) v = Wrbf[(row - 125) * HID + k];
        srows[idx] = v;
    }
    __syncthreads();
    int t = threadIdx.x;
    float acc[8];
    #pragma unroll
    for (int r = 0; r < 8; r++) acc[r] = 0.0f;
    for (int k = 0; k < HID; k++) {
        float w = W1[k * HID + t];
        #pragma unroll
        for (int r = 0; r < 8; r++)
            acc[r] = fmaf(srows[r * HID + k], w, acc[r]);
    }
    #pragma unroll
    for (int r = 0; r < 8; r++) {
        int row = r0 + r;
        float hi = __shfl_down_sync(0xffffffffu, acc[r], 1);
        if (row < 125) {
            g_E1[row * HID + t] = acc[r];
            if ((t & 1) == 0)
                g_E1h[row * (HID / 2) + (t >> 1)] = __floats2half2_rn(acc[r], hi);
        } else if (row < 189) {
            g_Wr1[(row - 125) * HID + t] = acc[r];
        }
    }
}

// ---------------- K4: tabulate g(d)=rbf(d)@Wr1 -> half2 pairs -----------
#define TROWS 16
__global__ void __launch_bounds__(256) k_table() {
    __shared__ float rb[NRBF * TROWS];
    __shared__ float rbx[NRBF];
    int t = threadIdx.x;
    int row0 = blockIdx.x * TROWS;
    float wr[NRBF];
    #pragma unroll
    for (int j = 0; j < NRBF; j++) wr[j] = g_Wr1[j * HID + t];

    const float step = CUTOFF / (TAB - 1);
    const float inv_w = (float)NRBF / CUTOFF;
    #pragma unroll
    for (int p = 0; p < (NRBF * TROWS) / 256; p++) {
        int idx = t + 256 * p;
        int j = idx >> 4, r = idx & 15;
        float d = (float)(row0 + r) * step;
        float c = (float)j * (CUTOFF / (NRBF - 1));
        float u = (d - c) * inv_w;
        rb[idx] = __expf(-0.5f * u * u);
    }
    if (t < NRBF) {
        float d = (float)(row0 + TROWS) * step;
        float c = (float)t * (CUTOFF / (NRBF - 1));
        float u = (d - c) * inv_w;
        rbx[t] = __expf(-0.5f * u * u);
    }
    __syncthreads();

    float acc[TROWS + 1];
    #pragma unroll
    for (int r = 0; r <= TROWS; r++) acc[r] = 0.0f;
    #pragma unroll
    for (int j = 0; j < NRBF; j++) {
        float w = wr[j];
        const float4* rp = (const float4*)&rb[j * TROWS];
        #pragma unroll
        for (int g4 = 0; g4 < TROWS / 4; g4++) {
            float4 v = rp[g4];
            acc[g4 * 4 + 0] = fmaf(v.x, w, acc[g4 * 4 + 0]);
            acc[g4 * 4 + 1] = fmaf(v.y, w, acc[g4 * 4 + 1]);
            acc[g4 * 4 + 2] = fmaf(v.z, w, acc[g4 * 4 + 2]);
            acc[g4 * 4 + 3] = fmaf(v.w, w, acc[g4 * 4 + 3]);
        }
        acc[TROWS] = fmaf(rbx[j], w, acc[TROWS]);
    }
    #pragma unroll
    for (int r = 0; r < TROWS; r++)
        g_Th[(row0 + r) * HID + t] = __floats2half2_rn(acc[r], acc[r + 1]);
}

// ---------------- K5: top-K (two-region compaction + successive-min) ----
__global__ void k_topk() {
    extern __shared__ unsigned long long smem_ll[];
    unsigned long long* lists = smem_ll;
    float4* tile = (float4*)(lists + 8 * CAP);
    int warp = threadIdx.x >> 5, lane = threadIdx.x & 31;
    int row = blockIdx.x * 8 + warp;
    bool rv = g_valid[row] != 0;
    float xi = g_px[row], yi = g_py[row], zi = g_pz[row], si = g_ps[row];
    unsigned long long* list = lists + warp * CAP;
    unsigned lanemask_lt = (1u << lane) - 1u;
    int nc = 0, fc = 0;

    for (int base = 0; base < N_TOT; base += TKTILE) {
        for (int idx = threadIdx.x; idx < TKTILE; idx += 256) {
            int j = base + idx;
            tile[idx] = (j < N_TOT)
                ? make_float4(g_px[j], g_py[j], g_pz[j], g_ps[j])
                : make_float4(0.f, 0.f, 0.f, 3.0e9f);
        }
        __syncthreads();
        if (rv) {
            int n = min(TKTILE, N_TOT - base);
            for (int e0 = 0; e0 < n; e0 += 32) {
                int e = e0 + lane;
                float4 q = tile[e];
                float d2 = si + q.w - 2.0f * ((xi * q.x + yi * q.y) + zi * q.z);
                int j = base + e;
                bool ok = (e < n) && (j != row) && (d2 <= 145.0f);
                bool nr = ok && (d2 <= NEAR2);
                bool fr = ok && !nr;
                unsigned long long key =
                    ((unsigned long long)__float_as_uint(fmaxf(d2, 0.0f)) << 32)
                    | (unsigned)j;
                unsigned mn = __ballot_sync(0xffffffffu, nr);
                unsigned mf = __ballot_sync(0xffffffffu, fr);
                if (nr) {
                    int p = nc + __popc(mn & lanemask_lt);
                    if (p < NCAP) list[p] = key;
                }
                if (fr) {
                    int p = fc + __popc(mf & lanemask_lt);
                    if (p < FCAP) list[NCAP + p] = key;
                }
                nc += __popc(mn);
                fc += __popc(mf);
            }
        }
        __syncthreads();
    }

    int len1 = 0, len2 = 0;
    if (rv) {
        len1 = min(nc, NCAP);
        len2 = (nc >= KNBR) ? 0 : min(fc, FCAP);
    }
    unsigned long long prev = 0;
    for (int e = 0; e < KNBR; e++) {
        unsigned long long best = ~0ull;
        for (int idx = lane; idx < len1; idx += 32) {
            unsigned long long v = list[idx];
            if (v > prev && v < best) best = v;
        }
        for (int idx = lane; idx < len2; idx += 32) {
            unsigned long long v = list[NCAP + idx];
            if (v > prev && v < best) best = v;
        }
        #pragma unroll
        for (int o = 16; o; o >>= 1) {
            unsigned long long ov = __shfl_down_sync(0xffffffffu, best, o);
            best = (ov < best) ? ov : best;
        }
        best = __shfl_sync(0xffffffffu, best, 0);
        if (lane == 0) {
            if (best == ~0ull) {
                g_nbr[row * KNBR + e] = 0;
                g_dq[row * KNBR + e] = BIGV;
            } else {
                float d2v = __uint_as_float((unsigned)(best >> 32));
                g_nbr[row * KNBR + e] = (int)(unsigned)(best & 0xffffffffu);
                g_dq[row * KNBR + e] = sqrtf(fmaxf(d2v, 1e-12f));
            }
        }
        prev = best;
    }
}

// ---------------- K6: per-edge z1 + silu (128 thr, 2 ch/thread) ---------
__global__ void __launch_bounds__(128) k_edges(const float* __restrict__ b1) {
    __shared__ float sf[KNBR];     // lerp fraction
    __shared__ int   si0[KNBR];    // table row * HID
    __shared__ int   szo[KNBR];    // zj * HID/2 (half2 index)
    __shared__ int   sok[KNBR];    // valid flag
    int i = blockIdx.x, t = threadIdx.x;
    const float sc = (float)(TAB - 1) / CUTOFF;
    if (t < KNBR) {
        float d = g_dq[i * KNBR + t];
        bool ok = d <= CUTOFF;
        float u = d * sc;
        int i0 = min((int)u, TAB - 2);
        sf[t] = ok ? (u - (float)i0) : 0.0f;
        si0[t] = ok ? i0 * HID : 0;
        szo[t] = g_zz[g_nbr[i * KNBR + t]] * (HID / 2);
        sok[t] = ok ? 1 : 0;
        unsigned m = __ballot_sync(0xffffffffu, ok);
        if (t == 0) g_cnt[i] = __popc(m);
    }
    __syncthreads();

    int zi = g_zz[i];
    float2 e1 = *(const float2*)&g_E1[zi * HID + 2 * t];
    float2 bb = *(const float2*)&b1[2 * t];
    float base0 = e1.x + bb.x;
    float base1 = e1.y + bb.y;
    float acc0 = 0.0f, acc1 = 0.0f;

    #pragma unroll 4
    for (int e = 0; e < KNBR; e++) {
        if (sok[e]) {
            float f = sf[e];
            __half2 pnh = g_E1h[szo[e] + t];
            uint2 thv = *(const uint2*)&g_Th[si0[e] + 2 * t];
            float2 pn = __half22float2(pnh);
            float2 gA = __half22float2(*(__half2*)&thv.x);
            float2 gB = __half22float2(*(__half2*)&thv.y);
            float g0 = fmaf(f, gA.y - gA.x, gA.x);
            float g1 = fmaf(f, gB.y - gB.x, gB.x);
            acc0 += fast_silu(base0 + pn.x + g0);
            acc1 += fast_silu(base1 + pn.y + g1);
        }
    }
    *(float2*)&g_s[i * HID + 2 * t] = make_float2(acc0, acc1);
}

// ---------------- K7: feat = h + s@W2 + cnt*b2 (reg-tiled f32x2 GEMM) ---
#define FBM 64
#define FBN 128
#define FBK 32
__global__ void __launch_bounds__(256) k_final(const float* __restrict__ embed,
                                               const float* __restrict__ W2,
                                               const float* __restrict__ b2,
                                               float* __restrict__ out) {
    __shared__ float As[FBM * FBK];
    __shared__ float Bs[FBK * FBN];
    int tid = threadIdx.x;
    int tx = tid & 31;
    int ty = tid >> 5;
    int m0 = blockIdx.x * FBM;
    int n0 = blockIdx.y * FBN;

    unsigned long long acc[16];
    #pragma unroll
    for (int q = 0; q < 16; q++) acc[q] = 0ull;

    for (int k0 = 0; k0 < HID; k0 += FBK) {
        #pragma unroll
        for (int p = 0; p < (FBM * FBK) / 256; p++) {
            int idx = tid + 256 * p;
            int m = idx >> 5, k = idx & 31;
            As[idx] = g_s[(m0 + m) * HID + k0 + k];
        }
        #pragma unroll
        for (int p = 0; p < (FBK * FBN) / 256; p++) {
            int idx = tid + 256 * p;
            int kk = idx >> 7, n = idx & 127;
            Bs[idx] = W2[(k0 + kk) * HID + n0 + n];
        }
        __syncthreads();
        #pragma unroll
        for (int kk4 = 0; kk4 < FBK; kk4 += 4) {
            float4 a4[8];
            #pragma unroll
            for (int r = 0; r < 8; r++)
                a4[r] = *(const float4*)&As[(ty * 8 + r) * FBK + kk4];
            #pragma unroll
            for (int j = 0; j < 4; j++) {
                float4 bv = *(const float4*)&Bs[(kk4 + j) * FBN + tx * 4];
                unsigned long long b01 = pk2(bv.x, bv.y);
                unsigned long long b23 = pk2(bv.z, bv.w);
                #pragma unroll
                for (int r = 0; r < 8; r++) {
                    float a = (j == 0) ? a4[r].x : (j == 1) ? a4[r].y
                             : (j == 2) ? a4[r].z : a4[r].w;
                    unsigned long long aa = pk2(a, a);
                    fma2(acc[r * 2 + 0], aa, b01);
                    fma2(acc[r * 2 + 1], aa, b23);
                }
            }
        }
        __syncthreads();
    }

    int cbase = n0 + tx * 4;
    float4 b2v = *(const float4*)&b2[cbase];
    #pragma unroll
    for (int r = 0; r < 8; r++) {
        int node = m0 + ty * 8 + r;
        float2 p0 = up2(acc[r * 2 + 0]);
        float2 p1 = up2(acc[r * 2 + 1]);
        float4 res = make_float4(0.f, 0.f, 0.f, 0.f);
        if (g_valid[node]) {
            const float* em = embed + g_zz[node] * HID + cbase;
            float cf = (float)g_cnt[node];
            res.x = em[0] + p0.x + cf * b2v.x;
            res.y = em[1] + p0.y + cf * b2v.y;
            res.z = em[2] + p1.x + cf * b2v.z;
            res.w = em[3] + p1.y + cf * b2v.w;
        }
        *(float4*)&out[node * HID + cbase] = res;
    }

    if (blockIdx.y == 0 && tid < FBM) {
        int node = m0 + tid;
        float vn = (node >= N_ATOMS && g_valid[node]) ? 1.0f : 0.0f;
        float pn = (node < N_ATOMS) ? 1.0f : 0.0f;
        out[N_TOT * HID + node] = vn;
        out[N_TOT * HID + N_TOT + node] = pn;
    }
}

// ---------------- launch -------------------------------------------------
extern "C" void kernel_launch(void* const* d_in, const int* in_sizes, int n_in,
                              void* d_out, int out_size) {
    const float* pos   = (const float*)d_in[0];
    const int*   anum  = (const int*)d_in[1];
    const float* cell  = (const float*)d_in[2];
    const float* embed = (const float*)d_in[3];
    const float* Wrbf  = (const float*)d_in[4];
    const float* W1    = (const float*)d_in[5];
    const float* b1    = (const float*)d_in[6];
    const float* W2    = (const float*)d_in[7];
    const float* b2    = (const float*)d_in[8];
    float* out = (float*)d_out;

    const int smem_topk = 8 * CAP * 8 + TKTILE * 16;   // 73728
    cudaFuncSetAttribute(k_topk, cudaFuncAttributeMaxDynamicSharedMemorySize, smem_topk);

    k_setup<<<(N_TOT + 255) / 256, 256>>>(pos, anum, cell);
    k_vmask<<<dim3((N_GRID + 255) / 256, VSPLIT), 256>>>();
    k_premm<<<(189 + 7) / 8, 256>>>(embed, Wrbf, W1);
    k_table<<<TAB / TROWS, 256>>>();
    k_topk<<<N_TOT / 8, 256, smem_topk>>>();
    k_edges<<<N_TOT, 128>>>(b1);
    k_final<<<dim3(N_TOT / FBM, HID / FBN), 256>>>(embed, W2, b2, out);
}